// round 4
// baseline (speedup 1.0000x reference)
#include <cuda_runtime.h>

#define NN 50000
#define EE 800000
#define HH 128
#define DD 3
#define EM 64      // rows (edges/nodes) per block
#define KC 64      // K tile rows
#define WS 136     // weight tile stride (floats)
#define SA 268     // edge layer-1 A stride (K padded to 264)
#define SN 260     // node layer-1 A stride (K = 256)
#define S2 132     // A2/Mm stride

// ---------------- device scratch ----------------
__device__ __align__(16) float g_agg[NN * HH];
__device__ __align__(16) float g_coordcnt[NN * 4];   // {cx, cy, cz, cnt}
// pre-rounded, pre-permuted weights (tile-ready layout)
__device__ __align__(16) float g_ew1p[264 * HH];
__device__ __align__(16) float g_ew2p[128 * HH];
__device__ __align__(16) float g_cw1p[128 * HH];
__device__ __align__(16) float g_nw1p[256 * HH];
__device__ __align__(16) float g_nw2p[128 * HH];

__device__ __forceinline__ float silu_f(float v) { return v / (1.0f + __expf(-v)); }
__device__ __forceinline__ float sigmoid_f(float v) { return 1.0f / (1.0f + __expf(-v)); }
__device__ __forceinline__ float tf32r(float v) {
    unsigned r; asm("cvt.rna.tf32.f32 %0, %1;" : "=r"(r) : "f"(v));
    return __uint_as_float(r);
}
__device__ __forceinline__ void mma_tf32(float c[4],
    unsigned a0, unsigned a1, unsigned a2, unsigned a3,
    unsigned b0, unsigned b1)
{
    asm volatile("mma.sync.aligned.m16n8k8.row.col.f32.tf32.tf32.f32 "
        "{%0,%1,%2,%3}, {%4,%5,%6,%7}, {%8,%9}, {%0,%1,%2,%3};\n"
        : "+f"(c[0]), "+f"(c[1]), "+f"(c[2]), "+f"(c[3])
        : "r"(a0), "r"(a1), "r"(a2), "r"(a3), "r"(b0), "r"(b1));
}
__device__ __forceinline__ void red_add_v4(float* p, float a, float b, float c, float d) {
    asm volatile("red.global.add.v4.f32 [%0], {%1,%2,%3,%4};"
                 :: "l"(p), "f"(a), "f"(b), "f"(c), "f"(d) : "memory");
}

__global__ void zero_kernel() {
    const int total = NN * HH + NN * 4;
    for (int i = blockIdx.x * blockDim.x + threadIdx.x; i < total;
         i += gridDim.x * blockDim.x) {
        if (i < NN * HH) g_agg[i] = 0.0f;
        else g_coordcnt[i - NN * HH] = 0.0f;
    }
}

// Pre-round (RNA tf32) + column-permute weights into tile-ready layout.
// perm: col' = (c&64) | (c&7)<<3 | (c>>3)&7  (so B-frags vectorize as LDS.128)
__global__ void prep_kernel(const float* __restrict__ EW1, const float* __restrict__ EW2,
                            const float* __restrict__ CW1, const float* __restrict__ NW1,
                            const float* __restrict__ NW2) {
    const int total = (264 + 128 + 128 + 256 + 128) * HH;   // 904*128
    for (int i = blockIdx.x * blockDim.x + threadIdx.x; i < total;
         i += gridDim.x * blockDim.x) {
        const int k = i >> 7, cp = i & 127;
        const int corig = (cp & 64) | ((cp & 7) << 3) | ((cp >> 3) & 7);
        if (k < 264) {
            g_ew1p[k * HH + cp] = (k < 258) ? tf32r(EW1[k * HH + corig]) : 0.0f;
        } else if (k < 392) {
            g_ew2p[(k - 264) * HH + cp] = tf32r(EW2[(k - 264) * HH + corig]);
        } else if (k < 520) {
            g_cw1p[(k - 392) * HH + cp] = tf32r(CW1[(k - 392) * HH + corig]);
        } else if (k < 776) {
            g_nw1p[(k - 520) * HH + cp] = tf32r(NW1[(k - 520) * HH + corig]);
        } else {
            g_nw2p[(k - 776) * HH + cp] = tf32r(NW2[(k - 776) * HH + corig]);
        }
    }
}

// Pipelined GEMM: acc[8][4] += A[64 rows, 0:Ktot] @ Wp[0:Ktot, 128]
// Wp: pre-rounded + pre-permuted global weights, row-stride 128.
// Weight tiles register-prefetched (double-buffered through pf[]).
// Entry __syncthreads() covers caller's smem A writes + prior Wt reads.
__device__ __forceinline__ void gemm_pl(
    const float* __restrict__ Wp, int Ktot,
    const float* As, int sa, float* Wt,
    float acc[8][4], int tid, int wm, int wn, int g, int t)
{
    const int ntiles = (Ktot + KC - 1) / KC;
    float4 pf[8];
    {
        const int kc0 = (Ktot < KC) ? Ktot : KC;
        const float4* src = (const float4*)Wp;
        #pragma unroll
        for (int j = 0; j < 8; ++j) {
            const int f = tid + j * 256;
            pf[j] = (f < kc0 * 32) ? src[f] : make_float4(0.f, 0.f, 0.f, 0.f);
        }
    }
    for (int tile = 0; tile < ntiles; ++tile) {
        const int k0 = tile * KC;
        const int kc = (Ktot - k0 < KC) ? (Ktot - k0) : KC;
        __syncthreads();
        #pragma unroll
        for (int j = 0; j < 8; ++j) {
            const int f = tid + j * 256;
            if (f < kc * 32)
                *(float4*)&Wt[(f >> 5) * WS + (f & 31) * 4] = pf[j];
        }
        if (tile + 1 < ntiles) {
            const int kr = Ktot - k0 - KC;
            const int kcn = (kr < KC) ? kr : KC;
            const float4* src = (const float4*)(Wp + (k0 + KC) * HH);
            #pragma unroll
            for (int j = 0; j < 8; ++j) {
                const int f = tid + j * 256;
                if (f < kcn * 32) pf[j] = src[f];
            }
        }
        __syncthreads();
        const int nch = kc >> 3;
        const float* arow  = As + (wm * 16 + g) * sa + t;
        const float* wbase = Wt + wn * 64 + g * 8;
        for (int kk = 0; kk < nch; ++kk) {
            const int ka = k0 + kk * 8;
            const unsigned a0 = __float_as_uint(arow[ka]);
            const unsigned a1 = __float_as_uint(arow[8 * sa + ka]);
            const unsigned a2 = __float_as_uint(arow[ka + 4]);
            const unsigned a3 = __float_as_uint(arow[8 * sa + ka + 4]);
            const float4 b0lo = *(const float4*)&wbase[(kk * 8 + t) * WS];
            const float4 b0hi = *(const float4*)&wbase[(kk * 8 + t) * WS + 4];
            const float4 b1lo = *(const float4*)&wbase[(kk * 8 + t + 4) * WS];
            const float4 b1hi = *(const float4*)&wbase[(kk * 8 + t + 4) * WS + 4];
            mma_tf32(acc[0], a0, a1, a2, a3, __float_as_uint(b0lo.x), __float_as_uint(b1lo.x));
            mma_tf32(acc[1], a0, a1, a2, a3, __float_as_uint(b0lo.y), __float_as_uint(b1lo.y));
            mma_tf32(acc[2], a0, a1, a2, a3, __float_as_uint(b0lo.z), __float_as_uint(b1lo.z));
            mma_tf32(acc[3], a0, a1, a2, a3, __float_as_uint(b0lo.w), __float_as_uint(b1lo.w));
            mma_tf32(acc[4], a0, a1, a2, a3, __float_as_uint(b0hi.x), __float_as_uint(b1hi.x));
            mma_tf32(acc[5], a0, a1, a2, a3, __float_as_uint(b0hi.y), __float_as_uint(b1hi.y));
            mma_tf32(acc[6], a0, a1, a2, a3, __float_as_uint(b0hi.z), __float_as_uint(b1hi.z));
            mma_tf32(acc[7], a0, a1, a2, a3, __float_as_uint(b0hi.w), __float_as_uint(b1hi.w));
        }
    }
}

__device__ __forceinline__ void acc_zero(float acc[8][4]) {
    #pragma unroll
    for (int i = 0; i < 8; ++i)
        #pragma unroll
        for (int j = 0; j < 4; ++j) acc[i][j] = 0.f;
}

__device__ __forceinline__ void epi_silu_store(
    float acc[8][4], float* Out, int s, const float* bias,
    int wm, int wn, int g, int t)
{
    const int r0 = wm * 16 + g;
    #pragma unroll
    for (int n8 = 0; n8 < 8; ++n8) {
        const int c = wn * 64 + n8 * 8 + 2 * t;
        const float b0 = bias[c], b1 = bias[c + 1];
        float2 lo, hi;
        lo.x = tf32r(silu_f(acc[n8][0] + b0));
        lo.y = tf32r(silu_f(acc[n8][1] + b1));
        hi.x = tf32r(silu_f(acc[n8][2] + b0));
        hi.y = tf32r(silu_f(acc[n8][3] + b1));
        *(float2*)&Out[r0 * s + c]       = lo;
        *(float2*)&Out[(r0 + 8) * s + c] = hi;
    }
}

// ---------------- fused edge kernel ----------------
__global__ __launch_bounds__(256, 2) void edge_kernel(
    const float* __restrict__ h, const float* __restrict__ x,
    const int* __restrict__ ei, const float* __restrict__ eattr,
    const float* __restrict__ eb1, const float* __restrict__ eb2,
    const float* __restrict__ cb1, const float* __restrict__ CW2,
    const float* __restrict__ AW, const float* __restrict__ ab)
{
    extern __shared__ float dsm[];
    float* A1 = dsm;               // [64][268]
    float* A2 = dsm;               // [64][132] alias
    float* Mm = dsm + EM * S2;     // [64][132]
    float* Wt = dsm + EM * SA;     // [64][136]

    __shared__ int   s_row[EM];
    __shared__ float s_cd[EM][3];
    __shared__ float s_att[EM];
    __shared__ float s_b1[HH], s_b2[HH], s_bc[HH], s_aw[HH], s_c2[HH];

    const int tid  = threadIdx.x;
    const int lane = tid & 31, warp = tid >> 5;
    const int g = lane >> 2, t = lane & 3;
    const int wm = warp & 3, wn = warp >> 2;
    const int e0 = blockIdx.x * EM;

    if (tid < HH) {
        s_b1[tid] = eb1[tid]; s_b2[tid] = eb2[tid]; s_bc[tid] = cb1[tid];
        s_aw[tid] = AW[tid];  s_c2[tid] = CW2[tid];
    }
    if (tid >= 128 && tid < 128 + EM) {
        const int e = tid - 128;
        const int idx = e0 + e;
        const int r = ei[idx], c = ei[EE + idx];
        s_row[e] = r;
        float rad = 0.f;
        #pragma unroll
        for (int d = 0; d < 3; ++d) {
            const float df = x[r * 3 + d] - x[c * 3 + d];
            s_cd[e][d] = df; rad += df * df;
        }
        A1[e * SA + 256] = tf32r(rad);
        A1[e * SA + 257] = tf32r(eattr[idx]);
        #pragma unroll
        for (int k = 258; k < 264; ++k) A1[e * SA + k] = 0.f;
    }
    {
        const int c4 = lane * 4;
        #pragma unroll
        for (int p = 0; p < 8; ++p) {
            const int e = p * 8 + warp;
            const int idx = e0 + e;
            const int r = ei[idx], c = ei[EE + idx];
            float4 vr = *(const float4*)&h[r * HH + c4];
            float4 vc = *(const float4*)&h[c * HH + c4];
            vr.x = tf32r(vr.x); vr.y = tf32r(vr.y); vr.z = tf32r(vr.z); vr.w = tf32r(vr.w);
            vc.x = tf32r(vc.x); vc.y = tf32r(vc.y); vc.z = tf32r(vc.z); vc.w = tf32r(vc.w);
            *(float4*)&A1[e * SA + c4]       = vr;
            *(float4*)&A1[e * SA + 128 + c4] = vc;
        }
    }

    float acc[8][4];

    // ---- layer 1 ----
    acc_zero(acc);
    gemm_pl(g_ew1p, 264, A1, SA, Wt, acc, tid, wm, wn, g, t);
    __syncthreads();
    epi_silu_store(acc, A2, S2, s_b1, wm, wn, g, t);

    // ---- layer 2 ----
    acc_zero(acc);
    gemm_pl(g_ew2p, 128, A2, S2, Wt, acc, tid, wm, wn, g, t);
    __syncthreads();
    epi_silu_store(acc, Mm, S2, s_b2, wm, wn, g, t);
    __syncthreads();

    // ---- attention gate ----
    {
        const int e = tid >> 2, q = tid & 3;
        float s = 0.f;
        const float* mrow = Mm + e * S2 + q * 32;
        const float* aw   = s_aw + q * 32;
        #pragma unroll
        for (int kk = 0; kk < 32; ++kk) s += mrow[kk] * aw[kk];
        s += __shfl_down_sync(0xffffffffu, s, 1);
        s += __shfl_down_sync(0xffffffffu, s, 2);
        if (q == 0) s_att[e] = sigmoid_f(s + ab[0]);
    }
    __syncthreads();

    // ---- gate + vectorized scatter ----
    #pragma unroll
    for (int p = 0; p < 8; ++p) {
        const int q = p * 256 + tid;
        const int e = q >> 5, c = (q & 31) * 4;
        float4 v = *(float4*)&Mm[e * S2 + c];
        const float a = s_att[e];
        v.x = tf32r(v.x * a); v.y = tf32r(v.y * a);
        v.z = tf32r(v.z * a); v.w = tf32r(v.w * a);
        *(float4*)&Mm[e * S2 + c] = v;
        red_add_v4(&g_agg[s_row[e] * HH + c], v.x, v.y, v.z, v.w);
    }

    // ---- coord MLP layer ----
    acc_zero(acc);
    gemm_pl(g_cw1p, 128, Mm, S2, Wt, acc, tid, wm, wn, g, t);
    __syncthreads();
    epi_silu_store(acc, A2, S2, s_bc, wm, wn, g, t);
    __syncthreads();

    // ---- coord_update + fused coord/count scatter ----
    {
        const int e = tid >> 2, q = tid & 3;
        float s = 0.f;
        const float* prow = A2 + e * S2 + q * 32;
        const float* c2   = s_c2 + q * 32;
        #pragma unroll
        for (int kk = 0; kk < 32; ++kk) s += prow[kk] * c2[kk];
        s += __shfl_down_sync(0xffffffffu, s, 1);
        s += __shfl_down_sync(0xffffffffu, s, 2);
        if (q == 0) {
            const int r = s_row[e];
            red_add_v4(&g_coordcnt[r * 4],
                       s_cd[e][0] * s, s_cd[e][1] * s, s_cd[e][2] * s, 1.0f);
        }
    }
}

// ---------------- tensorized node kernel ----------------
__global__ __launch_bounds__(256, 2) void node_kernel(
    const float* __restrict__ h, const float* __restrict__ x,
    const float* __restrict__ nb1, const float* __restrict__ nb2,
    float* __restrict__ out_h, float* __restrict__ out_x)
{
    extern __shared__ float dsm[];
    float* A1 = dsm;               // [64][260]
    float* A2 = dsm;               // [64][132] alias
    float* Wt = dsm + EM * SN;     // [64][136]

    __shared__ float s_nb1[HH], s_nb2[HH];

    const int tid  = threadIdx.x;
    const int lane = tid & 31, warp = tid >> 5;
    const int g = lane >> 2, t = lane & 3;
    const int wm = warp & 3, wn = warp >> 2;
    const int n0 = blockIdx.x * EM;

    if (tid < HH) { s_nb1[tid] = nb1[tid]; s_nb2[tid] = nb2[tid]; }
    {
        const int c4 = lane * 4;
        #pragma unroll
        for (int p = 0; p < 8; ++p) {
            const int n = p * 8 + warp;
            int r = n0 + n; if (r >= NN) r = NN - 1;
            float4 vh = *(const float4*)&h[r * HH + c4];
            float4 va = *(const float4*)&g_agg[r * HH + c4];
            vh.x = tf32r(vh.x); vh.y = tf32r(vh.y); vh.z = tf32r(vh.z); vh.w = tf32r(vh.w);
            va.x = tf32r(va.x); va.y = tf32r(va.y); va.z = tf32r(va.z); va.w = tf32r(va.w);
            *(float4*)&A1[n * SN + c4]       = vh;
            *(float4*)&A1[n * SN + 128 + c4] = va;
        }
    }

    float acc[8][4];
    acc_zero(acc);
    gemm_pl(g_nw1p, 256, A1, SN, Wt, acc, tid, wm, wn, g, t);
    __syncthreads();
    epi_silu_store(acc, A2, S2, s_nb1, wm, wn, g, t);

    acc_zero(acc);
    gemm_pl(g_nw2p, 128, A2, S2, Wt, acc, tid, wm, wn, g, t);

    // residual epilogue straight to gmem
    {
        const int r0 = n0 + wm * 16 + g;
        #pragma unroll
        for (int n8 = 0; n8 < 8; ++n8) {
            const int c = wn * 64 + n8 * 8 + 2 * t;
            const float b0 = s_nb2[c], b1 = s_nb2[c + 1];
            if (r0 < NN) {
                float2 v;
                v.x = h[r0 * HH + c]     + acc[n8][0] + b0;
                v.y = h[r0 * HH + c + 1] + acc[n8][1] + b1;
                *(float2*)&out_h[r0 * HH + c] = v;
            }
            if (r0 + 8 < NN) {
                float2 v;
                v.x = h[(r0 + 8) * HH + c]     + acc[n8][2] + b0;
                v.y = h[(r0 + 8) * HH + c + 1] + acc[n8][3] + b1;
                *(float2*)&out_h[(r0 + 8) * HH + c] = v;
            }
        }
    }

    if (tid < EM * DD) {
        const int n = tid / 3, d = tid % 3;
        const int r = n0 + n;
        if (r < NN) {
            float cnt = g_coordcnt[r * 4 + 3];
            cnt = (cnt < 1.0f) ? 1.0f : cnt;
            out_x[r * 3 + d] = x[r * 3 + d] + g_coordcnt[r * 4 + d] / cnt;
        }
    }
}

// ---------------- launch ----------------
extern "C" void kernel_launch(void* const* d_in, const int* in_sizes, int n_in,
                              void* d_out, int out_size) {
    const float* h     = (const float*)d_in[0];
    const float* x     = (const float*)d_in[1];
    const int*   ei    = (const int*)d_in[2];
    const float* eattr = (const float*)d_in[3];
    const float* EW1   = (const float*)d_in[4];
    const float* eb1   = (const float*)d_in[5];
    const float* EW2   = (const float*)d_in[6];
    const float* eb2   = (const float*)d_in[7];
    const float* NW1   = (const float*)d_in[8];
    const float* nb1   = (const float*)d_in[9];
    const float* NW2   = (const float*)d_in[10];
    const float* nb2   = (const float*)d_in[11];
    const float* CW1   = (const float*)d_in[12];
    const float* cb1   = (const float*)d_in[13];
    const float* CW2   = (const float*)d_in[14];
    const float* AW    = (const float*)d_in[15];
    const float* ab    = (const float*)d_in[16];

    float* out_h = (float*)d_out;
    float* out_x = (float*)d_out + (size_t)NN * HH;

    const int smem_edge = (EM * SA + KC * WS) * 4;   // 103,424 B
    const int smem_node = (EM * SN + KC * WS) * 4;   // 101,376 B
    cudaFuncSetAttribute(edge_kernel,
                         cudaFuncAttributeMaxDynamicSharedMemorySize, smem_edge);
    cudaFuncSetAttribute(node_kernel,
                         cudaFuncAttributeMaxDynamicSharedMemorySize, smem_node);

    zero_kernel<<<1024, 256>>>();
    prep_kernel<<<452, 256>>>(EW1, EW2, CW1, NW1, NW2);
    edge_kernel<<<EE / EM, 256, smem_edge>>>(h, x, ei, eattr,
                                             eb1, eb2, cb1, CW2, AW, ab);
    node_kernel<<<(NN + EM - 1) / EM, 256, smem_node>>>(h, x, nb1, nb2,
                                                        out_h, out_x);
}

// round 6
// speedup vs baseline: 1.1920x; 1.1920x over previous
#include <cuda_runtime.h>

#define NN 50000
#define EE 800000
#define HH 128
#define DD 3
#define EM 64      // rows (edges/nodes) per block
#define SA 268     // edge layer-1 A stride (K padded to 264)
#define SN 260     // node layer-1 A stride (K = 256)
#define S2 132     // A2/Mm stride

// ---------------- device scratch ----------------
__device__ __align__(16) float g_agg[NN * HH];
__device__ __align__(16) float g_coordcnt[NN * 4];   // {cx, cy, cz, cnt}
// pre-rounded, pre-permuted weights (fragment-ready layout)
__device__ __align__(16) float g_ew1p[264 * HH];
__device__ __align__(16) float g_ew2p[128 * HH];
__device__ __align__(16) float g_cw1p[128 * HH];
__device__ __align__(16) float g_nw1p[256 * HH];
__device__ __align__(16) float g_nw2p[128 * HH];

__device__ __forceinline__ float silu_f(float v) { return v / (1.0f + __expf(-v)); }
__device__ __forceinline__ float sigmoid_f(float v) { return 1.0f / (1.0f + __expf(-v)); }
__device__ __forceinline__ float tf32r(float v) {
    unsigned r; asm("cvt.rna.tf32.f32 %0, %1;" : "=r"(r) : "f"(v));
    return __uint_as_float(r);
}
__device__ __forceinline__ void mma_tf32(float c[4],
    unsigned a0, unsigned a1, unsigned a2, unsigned a3,
    unsigned b0, unsigned b1)
{
    asm volatile("mma.sync.aligned.m16n8k8.row.col.f32.tf32.tf32.f32 "
        "{%0,%1,%2,%3}, {%4,%5,%6,%7}, {%8,%9}, {%0,%1,%2,%3};\n"
        : "+f"(c[0]), "+f"(c[1]), "+f"(c[2]), "+f"(c[3])
        : "r"(a0), "r"(a1), "r"(a2), "r"(a3), "r"(b0), "r"(b1));
}
__device__ __forceinline__ void red_add_v4(float* p, float a, float b, float c, float d) {
    asm volatile("red.global.add.v4.f32 [%0], {%1,%2,%3,%4};"
                 :: "l"(p), "f"(a), "f"(b), "f"(c), "f"(d) : "memory");
}

__global__ void zero_kernel() {
    const int total = NN * HH + NN * 4;
    for (int i = blockIdx.x * blockDim.x + threadIdx.x; i < total;
         i += gridDim.x * blockDim.x) {
        if (i < NN * HH) g_agg[i] = 0.0f;
        else g_coordcnt[i - NN * HH] = 0.0f;
    }
}

// Pre-round (RNA tf32) + column-permute weights into fragment-ready layout.
// perm: col' = (c&64) | (c&7)<<3 | (c>>3)&7
__global__ void prep_kernel(const float* __restrict__ EW1, const float* __restrict__ EW2,
                            const float* __restrict__ CW1, const float* __restrict__ NW1,
                            const float* __restrict__ NW2) {
    const int total = (264 + 128 + 128 + 256 + 128) * HH;
    for (int i = blockIdx.x * blockDim.x + threadIdx.x; i < total;
         i += gridDim.x * blockDim.x) {
        const int k = i >> 7, cp = i & 127;
        const int corig = (cp & 64) | ((cp & 7) << 3) | ((cp >> 3) & 7);
        if (k < 264) {
            g_ew1p[k * HH + cp] = (k < 258) ? tf32r(EW1[k * HH + corig]) : 0.0f;
        } else if (k < 392) {
            g_ew2p[(k - 264) * HH + cp] = tf32r(EW2[(k - 264) * HH + corig]);
        } else if (k < 520) {
            g_cw1p[(k - 392) * HH + cp] = tf32r(CW1[(k - 392) * HH + corig]);
        } else if (k < 776) {
            g_nw1p[(k - 520) * HH + cp] = tf32r(NW1[(k - 520) * HH + corig]);
        } else {
            g_nw2p[(k - 776) * HH + cp] = tf32r(NW2[(k - 776) * HH + corig]);
        }
    }
}

// Direct GEMM: acc[16][4] += A[warp 32 rows, 0:Ktot] @ Wp[0:Ktot, warp 64 cols]
// A from smem (tf32-rounded); B fragments LDG'd straight from permuted global
// weights (L1/L2 hot). acc[mi*8+n8]: mi = 16-row half, n8 = 8-col group.
// Caller must __syncthreads() after writing As.
__device__ __forceinline__ void gemm_direct(
    const float* __restrict__ Wp, int Ktot,
    const float* As, int sa,
    float acc[16][4], int wm, int wn, int g, int t)
{
    const float* arow0 = As + (wm * 32 + g) * sa + t;
    const float* arow1 = arow0 + 16 * sa;
    const float* wrow  = Wp + t * HH + wn * 64 + g * 8;
    const int nch = Ktot >> 3;
    for (int kk = 0; kk < nch; ++kk) {
        const int ka = kk * 8;
        const unsigned a00 = __float_as_uint(arow0[ka]);
        const unsigned a01 = __float_as_uint(arow0[8 * sa + ka]);
        const unsigned a02 = __float_as_uint(arow0[ka + 4]);
        const unsigned a03 = __float_as_uint(arow0[8 * sa + ka + 4]);
        const unsigned a10 = __float_as_uint(arow1[ka]);
        const unsigned a11 = __float_as_uint(arow1[8 * sa + ka]);
        const unsigned a12 = __float_as_uint(arow1[ka + 4]);
        const unsigned a13 = __float_as_uint(arow1[8 * sa + ka + 4]);
        const float4 b0lo = *(const float4*)&wrow[ka * HH];
        const float4 b0hi = *(const float4*)&wrow[ka * HH + 4];
        const float4 b1lo = *(const float4*)&wrow[(ka + 4) * HH];
        const float4 b1hi = *(const float4*)&wrow[(ka + 4) * HH + 4];
        mma_tf32(acc[0],  a00, a01, a02, a03, __float_as_uint(b0lo.x), __float_as_uint(b1lo.x));
        mma_tf32(acc[1],  a00, a01, a02, a03, __float_as_uint(b0lo.y), __float_as_uint(b1lo.y));
        mma_tf32(acc[2],  a00, a01, a02, a03, __float_as_uint(b0lo.z), __float_as_uint(b1lo.z));
        mma_tf32(acc[3],  a00, a01, a02, a03, __float_as_uint(b0lo.w), __float_as_uint(b1lo.w));
        mma_tf32(acc[4],  a00, a01, a02, a03, __float_as_uint(b0hi.x), __float_as_uint(b1hi.x));
        mma_tf32(acc[5],  a00, a01, a02, a03, __float_as_uint(b0hi.y), __float_as_uint(b1hi.y));
        mma_tf32(acc[6],  a00, a01, a02, a03, __float_as_uint(b0hi.z), __float_as_uint(b1hi.z));
        mma_tf32(acc[7],  a00, a01, a02, a03, __float_as_uint(b0hi.w), __float_as_uint(b1hi.w));
        mma_tf32(acc[8],  a10, a11, a12, a13, __float_as_uint(b0lo.x), __float_as_uint(b1lo.x));
        mma_tf32(acc[9],  a10, a11, a12, a13, __float_as_uint(b0lo.y), __float_as_uint(b1lo.y));
        mma_tf32(acc[10], a10, a11, a12, a13, __float_as_uint(b0lo.z), __float_as_uint(b1lo.z));
        mma_tf32(acc[11], a10, a11, a12, a13, __float_as_uint(b0lo.w), __float_as_uint(b1lo.w));
        mma_tf32(acc[12], a10, a11, a12, a13, __float_as_uint(b0hi.x), __float_as_uint(b1hi.x));
        mma_tf32(acc[13], a10, a11, a12, a13, __float_as_uint(b0hi.y), __float_as_uint(b1hi.y));
        mma_tf32(acc[14], a10, a11, a12, a13, __float_as_uint(b0hi.z), __float_as_uint(b1hi.z));
        mma_tf32(acc[15], a10, a11, a12, a13, __float_as_uint(b0hi.w), __float_as_uint(b1hi.w));
    }
}

__device__ __forceinline__ void acc_zero(float acc[16][4]) {
    #pragma unroll
    for (int i = 0; i < 16; ++i)
        #pragma unroll
        for (int j = 0; j < 4; ++j) acc[i][j] = 0.f;
}

// epilogue: silu(acc + bias[col]) -> tf32-rounded -> Out (stride s)
__device__ __forceinline__ void epi_silu_store(
    float acc[16][4], float* Out, int s, const float* bias,
    int wm, int wn, int g, int t)
{
    #pragma unroll
    for (int mi = 0; mi < 2; ++mi) {
        const int r0 = wm * 32 + mi * 16 + g;
        #pragma unroll
        for (int n8 = 0; n8 < 8; ++n8) {
            const int c = wn * 64 + n8 * 8 + 2 * t;
            const float b0 = bias[c], b1 = bias[c + 1];
            float* a = acc[mi * 8 + n8];
            float2 lo, hi;
            lo.x = tf32r(silu_f(a[0] + b0));
            lo.y = tf32r(silu_f(a[1] + b1));
            hi.x = tf32r(silu_f(a[2] + b0));
            hi.y = tf32r(silu_f(a[3] + b1));
            *(float2*)&Out[r0 * s + c]       = lo;
            *(float2*)&Out[(r0 + 8) * s + c] = hi;
        }
    }
}

// ---------------- fused edge kernel ----------------
__global__ __launch_bounds__(128, 3) void edge_kernel(
    const float* __restrict__ h, const float* __restrict__ x,
    const int* __restrict__ ei, const float* __restrict__ eattr,
    const float* __restrict__ eb1, const float* __restrict__ eb2,
    const float* __restrict__ cb1, const float* __restrict__ CW2,
    const float* __restrict__ AW, const float* __restrict__ ab)
{
    extern __shared__ float dsm[];
    float* A1 = dsm;               // [64][268]
    float* A2 = dsm;               // [64][132] alias (dead A1 after layer 1)
    float* Mm = dsm + EM * S2;     // [64][132]

    __shared__ int   s_row[EM];
    __shared__ float s_cd[EM][3];
    __shared__ float s_att[EM];
    __shared__ float s_b1[HH], s_b2[HH], s_bc[HH], s_aw[HH], s_c2[HH];

    const int tid  = threadIdx.x;
    const int lane = tid & 31, warp = tid >> 5;
    const int g = lane >> 2, t = lane & 3;
    const int wm = warp & 1, wn = warp >> 1;
    const int e0 = blockIdx.x * EM;

    if (tid < HH) {
        s_b1[tid] = eb1[tid]; s_b2[tid] = eb2[tid]; s_bc[tid] = cb1[tid];
        s_aw[tid] = AW[tid];  s_c2[tid] = CW2[tid];
    }
    if (tid < EM) {
        const int e = tid;
        const int idx = e0 + e;
        const int r = ei[idx], c = ei[EE + idx];
        s_row[e] = r;
        float rad = 0.f;
        #pragma unroll
        for (int d = 0; d < 3; ++d) {
            const float df = x[r * 3 + d] - x[c * 3 + d];
            s_cd[e][d] = df; rad += df * df;
        }
        A1[e * SA + 256] = tf32r(rad);
        A1[e * SA + 257] = tf32r(eattr[idx]);
        #pragma unroll
        for (int k = 258; k < 264; ++k) A1[e * SA + k] = 0.f;
    }
    {
        const int c4 = lane * 4;
        #pragma unroll
        for (int p = 0; p < 16; ++p) {
            const int e = p * 4 + warp;
            const int idx = e0 + e;
            const int r = ei[idx], c = ei[EE + idx];
            float4 vr = *(const float4*)&h[r * HH + c4];
            float4 vc = *(const float4*)&h[c * HH + c4];
            vr.x = tf32r(vr.x); vr.y = tf32r(vr.y); vr.z = tf32r(vr.z); vr.w = tf32r(vr.w);
            vc.x = tf32r(vc.x); vc.y = tf32r(vc.y); vc.z = tf32r(vc.z); vc.w = tf32r(vc.w);
            *(float4*)&A1[e * SA + c4]       = vr;
            *(float4*)&A1[e * SA + 128 + c4] = vc;
        }
    }
    __syncthreads();

    float acc[16][4];

    // ---- layer 1: [64,264] @ [264,128] ----
    acc_zero(acc);
    gemm_direct(g_ew1p, 264, A1, SA, acc, wm, wn, g, t);
    __syncthreads();                    // A1 reads done before alias write
    epi_silu_store(acc, A2, S2, s_b1, wm, wn, g, t);
    __syncthreads();

    // ---- layer 2: [64,128] @ [128,128] ----
    acc_zero(acc);
    gemm_direct(g_ew2p, 128, A2, S2, acc, wm, wn, g, t);
    epi_silu_store(acc, Mm, S2, s_b2, wm, wn, g, t);
    __syncthreads();

    // ---- attention gate: 2 threads per edge ----
    {
        const int e = tid >> 1, q = tid & 1;
        float s = 0.f;
        const float* mrow = Mm + e * S2 + q * 64;
        const float* aw   = s_aw + q * 64;
        #pragma unroll
        for (int kk = 0; kk < 64; ++kk) s += mrow[kk] * aw[kk];
        s += __shfl_down_sync(0xffffffffu, s, 1);
        if (q == 0) s_att[e] = sigmoid_f(s + ab[0]);
    }
    __syncthreads();

    // ---- gate + vectorized scatter ----
    #pragma unroll
    for (int p = 0; p < 16; ++p) {
        const int q = p * 128 + tid;
        const int e = q >> 5, c = (q & 31) * 4;
        float4 v = *(float4*)&Mm[e * S2 + c];
        const float a = s_att[e];
        v.x = tf32r(v.x * a); v.y = tf32r(v.y * a);
        v.z = tf32r(v.z * a); v.w = tf32r(v.w * a);
        *(float4*)&Mm[e * S2 + c] = v;
        red_add_v4(&g_agg[s_row[e] * HH + c], v.x, v.y, v.z, v.w);
    }
    __syncthreads();

    // ---- coord MLP layer: [64,128] @ [128,128] ----
    acc_zero(acc);
    gemm_direct(g_cw1p, 128, Mm, S2, acc, wm, wn, g, t);
    epi_silu_store(acc, A2, S2, s_bc, wm, wn, g, t);
    __syncthreads();

    // ---- coord_update + fused coord/count scatter ----
    {
        const int e = tid >> 1, q = tid & 1;
        float s = 0.f;
        const float* prow = A2 + e * S2 + q * 64;
        const float* c2   = s_c2 + q * 64;
        #pragma unroll
        for (int kk = 0; kk < 64; ++kk) s += prow[kk] * c2[kk];
        s += __shfl_down_sync(0xffffffffu, s, 1);
        if (q == 0) {
            const int r = s_row[e];
            red_add_v4(&g_coordcnt[r * 4],
                       s_cd[e][0] * s, s_cd[e][1] * s, s_cd[e][2] * s, 1.0f);
        }
    }
}

// ---------------- tensorized node kernel ----------------
__global__ __launch_bounds__(128, 3) void node_kernel(
    const float* __restrict__ h, const float* __restrict__ x,
    const float* __restrict__ nb1, const float* __restrict__ nb2,
    float* __restrict__ out_h, float* __restrict__ out_x)
{
    extern __shared__ float dsm[];
    float* A1 = dsm;               // [64][260]
    float* A2 = dsm;               // [64][132] alias

    __shared__ float s_nb1[HH], s_nb2[HH];

    const int tid  = threadIdx.x;
    const int lane = tid & 31, warp = tid >> 5;
    const int g = lane >> 2, t = lane & 3;
    const int wm = warp & 1, wn = warp >> 1;
    const int n0 = blockIdx.x * EM;

    if (tid < HH) { s_nb1[tid] = nb1[tid]; s_nb2[tid] = nb2[tid]; }
    {
        const int c4 = lane * 4;
        #pragma unroll
        for (int p = 0; p < 16; ++p) {
            const int n = p * 4 + warp;
            int r = n0 + n; if (r >= NN) r = NN - 1;
            float4 vh = *(const float4*)&h[r * HH + c4];
            float4 va = *(const float4*)&g_agg[r * HH + c4];
            vh.x = tf32r(vh.x); vh.y = tf32r(vh.y); vh.z = tf32r(vh.z); vh.w = tf32r(vh.w);
            va.x = tf32r(va.x); va.y = tf32r(va.y); va.z = tf32r(va.z); va.w = tf32r(va.w);
            *(float4*)&A1[n * SN + c4]       = vh;
            *(float4*)&A1[n * SN + 128 + c4] = va;
        }
    }
    __syncthreads();

    float acc[16][4];
    acc_zero(acc);
    gemm_direct(g_nw1p, 256, A1, SN, acc, wm, wn, g, t);
    __syncthreads();
    epi_silu_store(acc, A2, S2, s_nb1, wm, wn, g, t);
    __syncthreads();

    acc_zero(acc);
    gemm_direct(g_nw2p, 128, A2, S2, acc, wm, wn, g, t);

    // residual epilogue straight to gmem
    #pragma unroll
    for (int mi = 0; mi < 2; ++mi) {
        const int r0 = n0 + wm * 32 + mi * 16 + g;
        #pragma unroll
        for (int n8 = 0; n8 < 8; ++n8) {
            const int c = wn * 64 + n8 * 8 + 2 * t;
            const float b0 = s_nb2[c], b1 = s_nb2[c + 1];
            const float* a = acc[mi * 8 + n8];
            if (r0 < NN) {
                float2 v;
                v.x = h[r0 * HH + c]     + a[0] + b0;
                v.y = h[r0 * HH + c + 1] + a[1] + b1;
                *(float2*)&out_h[r0 * HH + c] = v;
            }
            if (r0 + 8 < NN) {
                float2 v;
                v.x = h[(r0 + 8) * HH + c]     + a[2] + b0;
                v.y = h[(r0 + 8) * HH + c + 1] + a[3] + b1;
                *(float2*)&out_h[(r0 + 8) * HH + c] = v;
            }
        }
    }

    for (int i = tid; i < EM * DD; i += 128) {
        const int n = i / 3, d = i % 3;
        const int r = n0 + n;
        if (r < NN) {
            float cnt = g_coordcnt[r * 4 + 3];
            cnt = (cnt < 1.0f) ? 1.0f : cnt;
            out_x[r * 3 + d] = x[r * 3 + d] + g_coordcnt[r * 4 + d] / cnt;
        }
    }
}

// ---------------- launch ----------------
extern "C" void kernel_launch(void* const* d_in, const int* in_sizes, int n_in,
                              void* d_out, int out_size) {
    const float* h     = (const float*)d_in[0];
    const float* x     = (const float*)d_in[1];
    const int*   ei    = (const int*)d_in[2];
    const float* eattr = (const float*)d_in[3];
    const float* EW1   = (const float*)d_in[4];
    const float* eb1   = (const float*)d_in[5];
    const float* EW2   = (const float*)d_in[6];
    const float* eb2   = (const float*)d_in[7];
    const float* NW1   = (const float*)d_in[8];
    const float* nb1   = (const float*)d_in[9];
    const float* NW2   = (const float*)d_in[10];
    const float* nb2   = (const float*)d_in[11];
    const float* CW1   = (const float*)d_in[12];
    const float* cb1   = (const float*)d_in[13];
    const float* CW2   = (const float*)d_in[14];
    const float* AW    = (const float*)d_in[15];
    const float* ab    = (const float*)d_in[16];

    float* out_h = (float*)d_out;
    float* out_x = (float*)d_out + (size_t)NN * HH;

    const int smem_edge = EM * SA * 4;   // 68,608 B
    const int smem_node = EM * SN * 4;   // 66,560 B
    cudaFuncSetAttribute(edge_kernel,
                         cudaFuncAttributeMaxDynamicSharedMemorySize, smem_edge);
    cudaFuncSetAttribute(node_kernel,
                         cudaFuncAttributeMaxDynamicSharedMemorySize, smem_node);

    zero_kernel<<<1024, 256>>>();
    prep_kernel<<<452, 256>>>(EW1, EW2, CW1, NW1, NW2);
    edge_kernel<<<EE / EM, 128, smem_edge>>>(h, x, ei, eattr,
                                             eb1, eb2, cb1, CW2, AW, ab);
    node_kernel<<<(NN + EM - 1) / EM, 128, smem_node>>>(h, x, nb1, nb2,
                                                        out_h, out_x);
}

// round 8
// speedup vs baseline: 2.5021x; 2.0991x over previous
#include <cuda_runtime.h>

#define NN 50000
#define EE 800000
#define HH 128
#define DD 3
#define EM 64      // rows (edges/nodes) per block
#define SA1 132    // layer-1 A stride in u32 (bf16x2 pairs), 132%32=4 conflict-free
#define SM1 68     // M buffers stride in u32, 68%32=4 conflict-free

// ---------------- device scratch ----------------
__device__ __align__(16) float g_agg[NN * HH];
__device__ __align__(16) float g_coordcnt[NN * 4];   // {cx, cy, cz, cnt}
// fragment-prepacked bf16 weights: [chunk][p=0..7][lane=0..31] uint4
// uint4 = {b0(n8=2p), b1(2p), b0(2p+1), b1(2p+1)} for that lane
__device__ __align__(16) uint4 g_ew1f[16 * 256];   // K=256
__device__ __align__(16) uint4 g_ew2f[8 * 256];    // K=128
__device__ __align__(16) uint4 g_cw1f[8 * 256];    // K=128
__device__ __align__(16) uint4 g_nw1f[16 * 256];   // K=256
__device__ __align__(16) uint4 g_nw2f[8 * 256];    // K=128

__device__ __forceinline__ float silu_f(float v) { return v / (1.0f + __expf(-v)); }
__device__ __forceinline__ float sigmoid_f(float v) { return 1.0f / (1.0f + __expf(-v)); }

// pack two fp32 -> bf16x2 (lo in low half). PTX: first src -> high half.
__device__ __forceinline__ unsigned pack_bf2(float lo, float hi) {
    unsigned d; asm("cvt.rn.bf16x2.f32 %0, %1, %2;" : "=r"(d) : "f"(hi), "f"(lo));
    return d;
}
__device__ __forceinline__ float bf_lo(unsigned u) { return __uint_as_float(u << 16); }
__device__ __forceinline__ float bf_hi(unsigned u) { return __uint_as_float(u & 0xffff0000u); }

__device__ __forceinline__ void mma_bf16(float c[4],
    unsigned a0, unsigned a1, unsigned a2, unsigned a3,
    unsigned b0, unsigned b1)
{
    asm volatile("mma.sync.aligned.m16n8k16.row.col.f32.bf16.bf16.f32 "
        "{%0,%1,%2,%3}, {%4,%5,%6,%7}, {%8,%9}, {%0,%1,%2,%3};\n"
        : "+f"(c[0]), "+f"(c[1]), "+f"(c[2]), "+f"(c[3])
        : "r"(a0), "r"(a1), "r"(a2), "r"(a3), "r"(b0), "r"(b1));
}
__device__ __forceinline__ void red_add_v4(float* p, float a, float b, float c, float d) {
    asm volatile("red.global.add.v4.f32 [%0], {%1,%2,%3,%4};"
                 :: "l"(p), "f"(a), "f"(b), "f"(c), "f"(d) : "memory");
}

__global__ void zero_kernel() {
    const int total = NN * HH + NN * 4;
    for (int i = blockIdx.x * blockDim.x + threadIdx.x; i < total;
         i += gridDim.x * blockDim.x) {
        if (i < NN * HH) g_agg[i] = 0.0f;
        else g_coordcnt[i - NN * HH] = 0.0f;
    }
}

// Pack weights into bf16 mma fragment order.
// chunk kk covers K rows [16kk, 16kk+16); p covers col groups n8=2p,2p+1.
// b0(lane) = {W[k0+2t][n8*8+g], W[k0+2t+1][n8*8+g]}, b1 = rows +8,+9.
__global__ void prep_kernel(const float* __restrict__ EW1, const float* __restrict__ EW2,
                            const float* __restrict__ CW1, const float* __restrict__ NW1,
                            const float* __restrict__ NW2) {
    const int idx = blockIdx.x * blockDim.x + threadIdx.x;
    if (idx >= 56 * 256) return;
    const int chunk = idx >> 8;
    const int rem = idx & 255;
    const int p = rem >> 5, lane = rem & 31;
    const int t = lane & 3, g = lane >> 2;

    const float* W; uint4* dst; int kbase; int loc;
    if (chunk < 16)      { W = EW1; dst = g_ew1f; loc = chunk;      kbase = loc * 16; }
    else if (chunk < 24) { W = EW2; dst = g_ew2f; loc = chunk - 16; kbase = loc * 16; }
    else if (chunk < 32) { W = CW1; dst = g_cw1f; loc = chunk - 24; kbase = loc * 16; }
    else if (chunk < 48) { W = NW1; dst = g_nw1f; loc = chunk - 32; kbase = loc * 16; }
    else                 { W = NW2; dst = g_nw2f; loc = chunk - 48; kbase = loc * 16; }

    const int c0 = p * 16 + g;        // n8 = 2p
    const int c1 = c0 + 8;            // n8 = 2p + 1
    const int k0 = kbase + 2 * t;
    uint4 v;
    v.x = pack_bf2(W[k0 * HH + c0],       W[(k0 + 1) * HH + c0]);
    v.y = pack_bf2(W[(k0 + 8) * HH + c0], W[(k0 + 9) * HH + c0]);
    v.z = pack_bf2(W[k0 * HH + c1],       W[(k0 + 1) * HH + c1]);
    v.w = pack_bf2(W[(k0 + 8) * HH + c1], W[(k0 + 9) * HH + c1]);
    dst[loc * 256 + p * 32 + lane] = v;
}

// bf16 GEMM: acc[16][4] += A[warp 32 rows, K] @ W[K, warp 64 cols]
// A32: packed bf16x2 smem (pair index = col/2), stride sa (u32).
// Wf: fragment-prepacked global weights.
__device__ __forceinline__ void gemm_bf(
    const uint4* __restrict__ Wf, int nchunks,
    const unsigned* A32, int sa,
    float acc[16][4], int wm, int wn, int g, int t, int lane)
{
    const unsigned* arow0 = A32 + (wm * 32 + g) * sa + t;
    const unsigned* arow1 = arow0 + 16 * sa;
    const uint4* wc = Wf + wn * 128 + lane;
    for (int kk = 0; kk < nchunks; ++kk) {
        const int ka = kk * 8;
        const unsigned a00 = arow0[ka];
        const unsigned a01 = arow0[8 * sa + ka];
        const unsigned a02 = arow0[ka + 4];
        const unsigned a03 = arow0[8 * sa + ka + 4];
        const unsigned a10 = arow1[ka];
        const unsigned a11 = arow1[8 * sa + ka];
        const unsigned a12 = arow1[ka + 4];
        const unsigned a13 = arow1[8 * sa + ka + 4];
        const uint4 f0 = wc[kk * 256];
        const uint4 f1 = wc[kk * 256 + 32];
        const uint4 f2 = wc[kk * 256 + 64];
        const uint4 f3 = wc[kk * 256 + 96];
        mma_bf16(acc[0],  a00, a01, a02, a03, f0.x, f0.y);
        mma_bf16(acc[1],  a00, a01, a02, a03, f0.z, f0.w);
        mma_bf16(acc[2],  a00, a01, a02, a03, f1.x, f1.y);
        mma_bf16(acc[3],  a00, a01, a02, a03, f1.z, f1.w);
        mma_bf16(acc[4],  a00, a01, a02, a03, f2.x, f2.y);
        mma_bf16(acc[5],  a00, a01, a02, a03, f2.z, f2.w);
        mma_bf16(acc[6],  a00, a01, a02, a03, f3.x, f3.y);
        mma_bf16(acc[7],  a00, a01, a02, a03, f3.z, f3.w);
        mma_bf16(acc[8],  a10, a11, a12, a13, f0.x, f0.y);
        mma_bf16(acc[9],  a10, a11, a12, a13, f0.z, f0.w);
        mma_bf16(acc[10], a10, a11, a12, a13, f1.x, f1.y);
        mma_bf16(acc[11], a10, a11, a12, a13, f1.z, f1.w);
        mma_bf16(acc[12], a10, a11, a12, a13, f2.x, f2.y);
        mma_bf16(acc[13], a10, a11, a12, a13, f2.z, f2.w);
        mma_bf16(acc[14], a10, a11, a12, a13, f3.x, f3.y);
        mma_bf16(acc[15], a10, a11, a12, a13, f3.z, f3.w);
    }
}

__device__ __forceinline__ void acc_zero(float acc[16][4]) {
    #pragma unroll
    for (int i = 0; i < 16; ++i)
        #pragma unroll
        for (int j = 0; j < 4; ++j) acc[i][j] = 0.f;
}

// epilogue: silu(acc + bias) -> packed bf16x2 smem (stride s32 u32)
__device__ __forceinline__ void epi_silu_bf(
    float acc[16][4], unsigned* Out32, int s32, const float* bias,
    int wm, int wn, int g, int t)
{
    #pragma unroll
    for (int mi = 0; mi < 2; ++mi) {
        const int r0 = wm * 32 + mi * 16 + g;
        #pragma unroll
        for (int n8 = 0; n8 < 8; ++n8) {
            const int c = wn * 64 + n8 * 8 + 2 * t;
            const float b0 = bias[c], b1 = bias[c + 1];
            const float* a = acc[mi * 8 + n8];
            Out32[r0 * s32 + (c >> 1)] =
                pack_bf2(silu_f(a[0] + b0), silu_f(a[1] + b1));
            Out32[(r0 + 8) * s32 + (c >> 1)] =
                pack_bf2(silu_f(a[2] + b0), silu_f(a[3] + b1));
        }
    }
}

// ---------------- fused edge kernel ----------------
__global__ __launch_bounds__(128, 4) void edge_kernel(
    const float* __restrict__ h, const float* __restrict__ x,
    const int* __restrict__ ei, const float* __restrict__ eattr,
    const float* __restrict__ EW1,
    const float* __restrict__ eb1, const float* __restrict__ eb2,
    const float* __restrict__ cb1, const float* __restrict__ CW2,
    const float* __restrict__ AW, const float* __restrict__ ab)
{
    extern __shared__ unsigned dsm[];
    unsigned* A1 = dsm;                 // [64][132] u32 (layer-1 input pairs)
    unsigned* Mm = dsm;                 // [64][68] alias (A1 dead after GEMM1)
    unsigned* M1 = dsm + EM * SA1;      // [64][68] (layer-1 out; later P)
    unsigned* P  = M1;

    __shared__ int   s_row[EM];
    __shared__ float s_cd[EM][3];
    __shared__ float s_rad[EM], s_ea[EM], s_att[EM];
    __shared__ float s_b1[HH], s_b2[HH], s_bc[HH], s_aw[HH], s_c2[HH];
    __shared__ float s_wr[HH], s_we[HH];

    const int tid  = threadIdx.x;
    const int lane = tid & 31, warp = tid >> 5;
    const int g = lane >> 2, t = lane & 3;
    const int wm = warp & 1, wn = warp >> 1;
    const int e0 = blockIdx.x * EM;

    if (tid < HH) {
        s_b1[tid] = eb1[tid]; s_b2[tid] = eb2[tid]; s_bc[tid] = cb1[tid];
        s_aw[tid] = AW[tid];  s_c2[tid] = CW2[tid];
        s_wr[tid] = EW1[256 * HH + tid];
        s_we[tid] = EW1[257 * HH + tid];
    }
    if (tid < EM) {
        const int e = tid;
        const int idx = e0 + e;
        const int r = ei[idx], c = ei[EE + idx];
        s_row[e] = r;
        float rad = 0.f;
        #pragma unroll
        for (int d = 0; d < 3; ++d) {
            const float df = x[r * 3 + d] - x[c * 3 + d];
            s_cd[e][d] = df; rad += df * df;
        }
        s_rad[e] = rad;
        s_ea[e] = eattr[idx];
    }
    // gather h[row], h[col], pack to bf16x2
    #pragma unroll
    for (int p = 0; p < 16; ++p) {
        const int e = p * 4 + warp;
        const int idx = e0 + e;
        const int r = ei[idx], c = ei[EE + idx];
        const float4 vr = *(const float4*)&h[r * HH + lane * 4];
        const float4 vc = *(const float4*)&h[c * HH + lane * 4];
        uint2 ur, uc;
        ur.x = pack_bf2(vr.x, vr.y); ur.y = pack_bf2(vr.z, vr.w);
        uc.x = pack_bf2(vc.x, vc.y); uc.y = pack_bf2(vc.z, vc.w);
        *(uint2*)&A1[e * SA1 + lane * 2]      = ur;   // pairs 0..63
        *(uint2*)&A1[e * SA1 + 64 + lane * 2] = uc;   // pairs 64..127
    }
    __syncthreads();

    float acc[16][4];

    // ---- layer 1: K=256 bf16 + fp32 rank-2 tail (radial, eattr) ----
    acc_zero(acc);
    gemm_bf(g_ew1f, 16, A1, SA1, acc, wm, wn, g, t, lane);
    #pragma unroll
    for (int mi = 0; mi < 2; ++mi) {
        const int r = wm * 32 + mi * 16 + g;
        const float r0 = s_rad[r], r1 = s_rad[r + 8];
        const float e0f = s_ea[r], e1f = s_ea[r + 8];
        #pragma unroll
        for (int n8 = 0; n8 < 8; ++n8) {
            const int c = wn * 64 + n8 * 8 + 2 * t;
            float* a = acc[mi * 8 + n8];
            a[0] += r0 * s_wr[c]     + e0f * s_we[c];
            a[1] += r0 * s_wr[c + 1] + e0f * s_we[c + 1];
            a[2] += r1 * s_wr[c]     + e1f * s_we[c];
            a[3] += r1 * s_wr[c + 1] + e1f * s_we[c + 1];
        }
    }
    epi_silu_bf(acc, M1, SM1, s_b1, wm, wn, g, t);
    __syncthreads();

    // ---- layer 2: K=128 ----
    acc_zero(acc);
    gemm_bf(g_ew2f, 8, M1, SM1, acc, wm, wn, g, t, lane);
    epi_silu_bf(acc, Mm, SM1, s_b2, wm, wn, g, t);   // Mm aliases dead A1
    __syncthreads();

    // ---- attention gate: 2 threads per edge ----
    {
        const int e = tid >> 1, q = tid & 1;
        const unsigned* mrow = Mm + e * SM1 + q * 32;
        const float* aw = s_aw + q * 64;
        float s = 0.f;
        #pragma unroll
        for (int k = 0; k < 32; ++k) {
            const unsigned u = mrow[k];
            s += bf_lo(u) * aw[2 * k] + bf_hi(u) * aw[2 * k + 1];
        }
        s += __shfl_down_sync(0xffffffffu, s, 1);
        if (q == 0) s_att[e] = sigmoid_f(s + ab[0]);
    }
    __syncthreads();

    // ---- gate + vectorized scatter (fp32 values into g_agg) ----
    #pragma unroll
    for (int p = 0; p < 16; ++p) {
        const int q = p * 128 + tid;
        const int e = q >> 5, j = q & 31;        // j = group of 4 cols
        unsigned* base = Mm + e * SM1 + 2 * j;
        const float a = s_att[e];
        const unsigned u0 = base[0], u1 = base[1];
        const float f0 = bf_lo(u0) * a, f1 = bf_hi(u0) * a;
        const float f2 = bf_lo(u1) * a, f3 = bf_hi(u1) * a;
        red_add_v4(&g_agg[s_row[e] * HH + 4 * j], f0, f1, f2, f3);
        base[0] = pack_bf2(f0, f1);
        base[1] = pack_bf2(f2, f3);
    }
    __syncthreads();

    // ---- coord MLP layer: K=128 ----
    acc_zero(acc);
    gemm_bf(g_cw1f, 8, Mm, SM1, acc, wm, wn, g, t, lane);
    epi_silu_bf(acc, P, SM1, s_bc, wm, wn, g, t);    // P aliases dead M1
    __syncthreads();

    // ---- coord_update + fused coord/count scatter ----
    {
        const int e = tid >> 1, q = tid & 1;
        const unsigned* prow = P + e * SM1 + q * 32;
        const float* c2 = s_c2 + q * 64;
        float s = 0.f;
        #pragma unroll
        for (int k = 0; k < 32; ++k) {
            const unsigned u = prow[k];
            s += bf_lo(u) * c2[2 * k] + bf_hi(u) * c2[2 * k + 1];
        }
        s += __shfl_down_sync(0xffffffffu, s, 1);
        if (q == 0) {
            const int r = s_row[e];
            red_add_v4(&g_coordcnt[r * 4],
                       s_cd[e][0] * s, s_cd[e][1] * s, s_cd[e][2] * s, 1.0f);
        }
    }
}

// ---------------- node kernel ----------------
__global__ __launch_bounds__(128, 4) void node_kernel(
    const float* __restrict__ h, const float* __restrict__ x,
    const float* __restrict__ nb1, const float* __restrict__ nb2,
    float* __restrict__ out_h, float* __restrict__ out_x)
{
    extern __shared__ unsigned dsm[];
    unsigned* A1 = dsm;                 // [64][132]
    unsigned* M1 = dsm + EM * SA1;      // [64][68]

    __shared__ float s_nb1[HH], s_nb2[HH];

    const int tid  = threadIdx.x;
    const int lane = tid & 31, warp = tid >> 5;
    const int g = lane >> 2, t = lane & 3;
    const int wm = warp & 1, wn = warp >> 1;
    const int n0 = blockIdx.x * EM;

    if (tid < HH) { s_nb1[tid] = nb1[tid]; s_nb2[tid] = nb2[tid]; }
    #pragma unroll
    for (int p = 0; p < 16; ++p) {
        const int n = p * 4 + warp;
        int r = n0 + n; if (r >= NN) r = NN - 1;
        const float4 vh = *(const float4*)&h[r * HH + lane * 4];
        const float4 va = *(const float4*)&g_agg[r * HH + lane * 4];
        uint2 uh, ua;
        uh.x = pack_bf2(vh.x, vh.y); uh.y = pack_bf2(vh.z, vh.w);
        ua.x = pack_bf2(va.x, va.y); ua.y = pack_bf2(va.z, va.w);
        *(uint2*)&A1[n * SA1 + lane * 2]      = uh;
        *(uint2*)&A1[n * SA1 + 64 + lane * 2] = ua;
    }
    __syncthreads();

    float acc[16][4];
    acc_zero(acc);
    gemm_bf(g_nw1f, 16, A1, SA1, acc, wm, wn, g, t, lane);
    epi_silu_bf(acc, M1, SM1, s_nb1, wm, wn, g, t);
    __syncthreads();

    acc_zero(acc);
    gemm_bf(g_nw2f, 8, M1, SM1, acc, wm, wn, g, t, lane);

    // residual epilogue straight to gmem (fp32)
    #pragma unroll
    for (int mi = 0; mi < 2; ++mi) {
        const int r0 = n0 + wm * 32 + mi * 16 + g;
        #pragma unroll
        for (int n8 = 0; n8 < 8; ++n8) {
            const int c = wn * 64 + n8 * 8 + 2 * t;
            const float b0 = s_nb2[c], b1 = s_nb2[c + 1];
            const float* a = acc[mi * 8 + n8];
            if (r0 < NN) {
                float2 v;
                v.x = h[r0 * HH + c]     + a[0] + b0;
                v.y = h[r0 * HH + c + 1] + a[1] + b1;
                *(float2*)&out_h[r0 * HH + c] = v;
            }
            if (r0 + 8 < NN) {
                float2 v;
                v.x = h[(r0 + 8) * HH + c]     + a[2] + b0;
                v.y = h[(r0 + 8) * HH + c + 1] + a[3] + b1;
                *(float2*)&out_h[(r0 + 8) * HH + c] = v;
            }
        }
    }

    for (int i = tid; i < EM * DD; i += 128) {
        const int n = i / 3, d = i % 3;
        const int r = n0 + n;
        if (r < NN) {
            float cnt = g_coordcnt[r * 4 + 3];
            cnt = (cnt < 1.0f) ? 1.0f : cnt;
            out_x[r * 3 + d] = x[r * 3 + d] + g_coordcnt[r * 4 + d] / cnt;
        }
    }
}

// ---------------- launch ----------------
extern "C" void kernel_launch(void* const* d_in, const int* in_sizes, int n_in,
                              void* d_out, int out_size) {
    const float* h     = (const float*)d_in[0];
    const float* x     = (const float*)d_in[1];
    const int*   ei    = (const int*)d_in[2];
    const float* eattr = (const float*)d_in[3];
    const float* EW1   = (const float*)d_in[4];
    const float* eb1   = (const float*)d_in[5];
    const float* EW2   = (const float*)d_in[6];
    const float* eb2   = (const float*)d_in[7];
    const float* NW1   = (const float*)d_in[8];
    const float* nb1   = (const float*)d_in[9];
    const float* NW2   = (const float*)d_in[10];
    const float* nb2   = (const float*)d_in[11];
    const float* CW1   = (const float*)d_in[12];
    const float* cb1   = (const float*)d_in[13];
    const float* CW2   = (const float*)d_in[14];
    const float* AW    = (const float*)d_in[15];
    const float* ab    = (const float*)d_in[16];

    float* out_h = (float*)d_out;
    float* out_x = (float*)d_out + (size_t)NN * HH;

    const int smem_bytes = (EM * SA1 + EM * SM1) * 4;   // 51,200 B
    cudaFuncSetAttribute(edge_kernel,
                         cudaFuncAttributeMaxDynamicSharedMemorySize, smem_bytes);
    cudaFuncSetAttribute(node_kernel,
                         cudaFuncAttributeMaxDynamicSharedMemorySize, smem_bytes);

    zero_kernel<<<1024, 256>>>();
    prep_kernel<<<56, 256>>>(EW1, EW2, CW1, NW1, NW2);
    edge_kernel<<<EE / EM, 128, smem_bytes>>>(h, x, ei, eattr, EW1,
                                              eb1, eb2, cb1, CW2, AW, ab);
    node_kernel<<<(NN + EM - 1) / EM, 128, smem_bytes>>>(h, x, nb1, nb2,
                                                         out_h, out_x);
}